// round 1
// baseline (speedup 1.0000x reference)
#include <cuda_runtime.h>
#include <math.h>

// Problem constants
constexpr int S_   = 81;     // sequence length
constexpr int D_   = 64;     // head dim
constexpr int ER_  = 163;    // emb table rows (2S-1)
constexpr int QSTR_ = 68;    // padded row stride (floats) for Q/K/E/V tiles (64+4 -> conflict-free float4 LDS)
constexpr int MSTR_ = 164;   // row stride for M = Q @ E^T
constexpr int PSTR_ = 84;    // row stride for logits / probs
constexpr int NT_  = 256;    // threads per CTA
constexpr int NW_  = 8;      // warps
constexpr int NTILE_ = 21;   // ceil(81/4) row tiles of 4

constexpr int SZ_Q  = S_ * QSTR_;    // 5508 floats
constexpr int SZ_K  = S_ * QSTR_;
constexpr int SZ_EV = ER_ * QSTR_;   // 11084 floats (E first, V reuses rows 0..80 later)
constexpr int SZ_M  = S_ * MSTR_;    // 13284 floats
constexpr int SZ_P  = S_ * PSTR_;    // 6804 floats
constexpr int SMEM_FLOATS = SZ_Q + SZ_K + SZ_EV + SZ_M + SZ_P;  // 42188 -> 168752 bytes

__global__ __launch_bounds__(NT_, 1)
void rpsa_kernel(const float* __restrict__ Qg_, const float* __restrict__ Kg_,
                 const float* __restrict__ Vg_, const float* __restrict__ Eg,
                 const int* __restrict__ causal_p, float* __restrict__ outg_)
{
    extern __shared__ float sm[];
    float* sQ  = sm;
    float* sK  = sQ + SZ_Q;
    float* sEV = sK + SZ_K;    // E table; later V (rows 0..80)
    float* sM  = sEV + SZ_EV;  // M[i][c] = Q[i] . E[c]
    float* sP  = sM + SZ_M;    // logits -> probs

    const int bh   = blockIdx.x;
    const int tid  = threadIdx.x;
    const int warp = tid >> 5;
    const int lane = tid & 31;
    const int causal = *causal_p;
    const float scale = 0.03608439182435161f;  // 1/sqrt(768)

    const float* Qg = Qg_ + (size_t)bh * (S_ * D_);
    const float* Kg = Kg_ + (size_t)bh * (S_ * D_);
    const float* Vg = Vg_ + (size_t)bh * (S_ * D_);
    float*     outg = outg_ + (size_t)bh * (S_ * D_);

    // ---------------- Stage A: load Q, K, E into SMEM (float4, coalesced) -------------
    #pragma unroll 1
    for (int t = tid; t < (S_ * D_) / 4; t += NT_) {
        int e = t << 2, r = e >> 6, c = e & 63;
        *(float4*)&sQ[r * QSTR_ + c] = *(const float4*)&Qg[e];
        *(float4*)&sK[r * QSTR_ + c] = *(const float4*)&Kg[e];
    }
    #pragma unroll 1
    for (int t = tid; t < (ER_ * D_) / 4; t += NT_) {
        int e = t << 2, r = e >> 6, c = e & 63;
        *(float4*)&sEV[r * QSTR_ + c] = *(const float4*)&Eg[e];
    }
    __syncthreads();

    // ---------------- Stage B: GEMM2  M[i][c] = Q[i] . E[c] --------------------------
    // causal: only columns c >= S-1 = 80 are ever gathered (rel = 80+i-j, j<=i).
    {
        const int c0 = causal ? (S_ - 1) : 0;
        const int ng = causal ? 3 : 6;   // column groups of 32 lanes
        for (int tile = warp; tile < NTILE_; tile += NW_) {
            const int i0 = tile * 4;
            float acc[4][6];
            #pragma unroll
            for (int r = 0; r < 4; r++)
                #pragma unroll
                for (int g = 0; g < 6; g++) acc[r][g] = 0.f;
            int ri[4], ci[6];
            #pragma unroll
            for (int r = 0; r < 4; r++) ri[r] = min(i0 + r, S_ - 1) * QSTR_;
            #pragma unroll
            for (int g = 0; g < 6; g++) ci[g] = min(c0 + lane + 32 * g, ER_ - 1) * QSTR_;

            for (int d = 0; d < D_; d += 4) {
                float4 q[4];
                #pragma unroll
                for (int r = 0; r < 4; r++) q[r] = *(const float4*)&sQ[ri[r] + d];
                #pragma unroll
                for (int g = 0; g < 6; g++) {
                    if (g < ng) {
                        float4 e4 = *(const float4*)&sEV[ci[g] + d];
                        #pragma unroll
                        for (int r = 0; r < 4; r++) {
                            acc[r][g] = fmaf(q[r].x, e4.x, acc[r][g]);
                            acc[r][g] = fmaf(q[r].y, e4.y, acc[r][g]);
                            acc[r][g] = fmaf(q[r].z, e4.z, acc[r][g]);
                            acc[r][g] = fmaf(q[r].w, e4.w, acc[r][g]);
                        }
                    }
                }
            }
            #pragma unroll
            for (int r = 0; r < 4; r++) {
                int i = i0 + r;
                if (i < S_) {
                    #pragma unroll
                    for (int g = 0; g < 6; g++) {
                        if (g < ng) {
                            int c = c0 + lane + 32 * g;
                            if (c < ER_) sM[i * MSTR_ + c] = acc[r][g];
                        }
                    }
                }
            }
        }
    }
    __syncthreads();

    // ---------------- Stage C: GEMM1 + bias gather + mask -> sP ----------------------
    for (int tile = warp; tile < NTILE_; tile += NW_) {
        const int i0   = tile * 4;
        const int imax = min(i0 + 3, S_ - 1);
        const int njj  = causal ? ((imax >> 5) + 1) : 3;   // skip j-groups above diagonal
        float acc[4][3];
        #pragma unroll
        for (int r = 0; r < 4; r++) { acc[r][0] = acc[r][1] = acc[r][2] = 0.f; }
        int ri[4], ji[3];
        #pragma unroll
        for (int r = 0; r < 4; r++) ri[r] = min(i0 + r, S_ - 1) * QSTR_;
        #pragma unroll
        for (int jj = 0; jj < 3; jj++) ji[jj] = min(lane + 32 * jj, S_ - 1) * QSTR_;

        for (int d = 0; d < D_; d += 4) {
            float4 q[4];
            #pragma unroll
            for (int r = 0; r < 4; r++) q[r] = *(const float4*)&sQ[ri[r] + d];
            #pragma unroll
            for (int jj = 0; jj < 3; jj++) {
                if (jj < njj) {
                    float4 k4 = *(const float4*)&sK[ji[jj] + d];
                    #pragma unroll
                    for (int r = 0; r < 4; r++) {
                        acc[r][jj] = fmaf(q[r].x, k4.x, acc[r][jj]);
                        acc[r][jj] = fmaf(q[r].y, k4.y, acc[r][jj]);
                        acc[r][jj] = fmaf(q[r].z, k4.z, acc[r][jj]);
                        acc[r][jj] = fmaf(q[r].w, k4.w, acc[r][jj]);
                    }
                }
            }
        }
        #pragma unroll
        for (int r = 0; r < 4; r++) {
            int i = i0 + r;
            if (i < S_) {
                #pragma unroll
                for (int jj = 0; jj < 3; jj++) {
                    int j = lane + 32 * jj;
                    if (j < S_) {
                        float v;
                        if (causal && j > i) v = -1.0e9f;
                        else v = (acc[r][jj] + sM[i * MSTR_ + (S_ - 1 + i - j)]) * scale;
                        sP[i * PSTR_ + j] = v;
                    }
                }
            }
        }
    }

    // V load overlapped with tail of GEMM1 (E region no longer needed: synced after B)
    #pragma unroll 1
    for (int t = tid; t < (S_ * D_) / 4; t += NT_) {
        int e = t << 2, r = e >> 6, c = e & 63;
        *(float4*)&sEV[r * QSTR_ + c] = *(const float4*)&Vg[e];
    }
    __syncthreads();

    // ---------------- Stage D: softmax (one warp per row) ----------------------------
    for (int i = warp; i < S_; i += NW_) {
        float* row = &sP[i * PSTR_];
        float a = row[lane];
        float b = row[lane + 32];
        float c = (lane < S_ - 64) ? row[lane + 64] : -3.0e38f;
        float m = fmaxf(a, fmaxf(b, c));
        #pragma unroll
        for (int o = 16; o > 0; o >>= 1) m = fmaxf(m, __shfl_xor_sync(0xffffffffu, m, o));
        float e0 = expf(a - m), e1 = expf(b - m);
        float e2 = (lane < S_ - 64) ? expf(c - m) : 0.f;
        float s = e0 + e1 + e2;
        #pragma unroll
        for (int o = 16; o > 0; o >>= 1) s += __shfl_xor_sync(0xffffffffu, s, o);
        float inv = 1.0f / s;
        row[lane]      = e0 * inv;
        row[lane + 32] = e1 * inv;
        if (lane < S_ - 64) row[lane + 64] = e2 * inv;
    }
    __syncthreads();

    // ---------------- Stage E: PV  out[i][d] = sum_j P[i][j] * V[j][d] ---------------
    for (int tile = warp; tile < NTILE_; tile += NW_) {
        const int i0   = tile * 4;
        const int imax = min(i0 + 3, S_ - 1);
        const int jmax = causal ? imax : (S_ - 1);   // masked P entries are exactly 0
        float2 acc[4];
        #pragma unroll
        for (int r = 0; r < 4; r++) { acc[r].x = 0.f; acc[r].y = 0.f; }
        int ri[4];
        #pragma unroll
        for (int r = 0; r < 4; r++) ri[r] = min(i0 + r, S_ - 1) * PSTR_;
        const int dcol = 2 * lane;

        for (int j = 0; j <= jmax; j++) {
            float2 v = *(const float2*)&sEV[j * QSTR_ + dcol];
            #pragma unroll
            for (int r = 0; r < 4; r++) {
                float p = sP[ri[r] + j];
                acc[r].x = fmaf(p, v.x, acc[r].x);
                acc[r].y = fmaf(p, v.y, acc[r].y);
            }
        }
        #pragma unroll
        for (int r = 0; r < 4; r++) {
            int i = i0 + r;
            if (i < S_) *(float2*)&outg[i * D_ + dcol] = acc[r];
        }
    }
}

extern "C" void kernel_launch(void* const* d_in, const int* in_sizes, int n_in,
                              void* d_out, int out_size)
{
    const float* Q  = (const float*)d_in[0];
    const float* K  = (const float*)d_in[1];
    const float* V  = (const float*)d_in[2];
    const float* E  = (const float*)d_in[3];
    const int*   uc = (const int*)d_in[4];
    float* out = (float*)d_out;

    const int nbh = out_size / (S_ * D_);   // 4096 for the bench shape
    const size_t smem = (size_t)SMEM_FLOATS * sizeof(float);  // 168752 B

    cudaFuncSetAttribute(rpsa_kernel, cudaFuncAttributeMaxDynamicSharedMemorySize, (int)smem);
    rpsa_kernel<<<nbh, NT_, smem>>>(Q, K, V, E, uc, out);
}

// round 2
// speedup vs baseline: 1.5666x; 1.5666x over previous
#include <cuda_runtime.h>
#include <math.h>

// Problem constants
constexpr int S_    = 81;    // sequence length
constexpr int D_    = 64;    // head dim
constexpr int ER_   = 163;   // emb table rows (2S-1)
constexpr int QSTR_ = 68;    // padded row stride (floats): 68 mod 32 = 4 -> conflict-free float4 LDS across rows
constexpr int PSTR_ = 81;    // row stride for logits/probs (row-contiguous or broadcast access only)
constexpr int NT_   = 256;   // threads per CTA
constexpr int NW_   = 8;     // warps
constexpr int NTILE_= 21;    // ceil(81/4) row tiles of 4

constexpr int SZ_Q  = S_ * QSTR_;   // 5508
constexpr int SZ_K  = S_ * QSTR_;   // 5508
constexpr int SZ_EV = ER_ * QSTR_;  // 11084 (E table; V reuses rows 0..80 after stage C)
constexpr int SZ_P  = S_ * PSTR_;   // 6561
constexpr int SMEM_FLOATS = SZ_Q + SZ_K + SZ_EV + SZ_P;  // 28661 floats = 114644 B -> 2 CTAs/SM

__global__ __launch_bounds__(NT_, 1)
void rpsa_kernel(const float* __restrict__ Qg_, const float* __restrict__ Kg_,
                 const float* __restrict__ Vg_, const float* __restrict__ Eg,
                 const int* __restrict__ causal_p, float* __restrict__ outg_)
{
    extern __shared__ float sm[];
    float* sQ  = sm;
    float* sK  = sQ + SZ_Q;
    float* sEV = sK + SZ_K;    // E table during QK+bias; V afterwards
    float* sP  = sEV + SZ_EV;  // logits -> probs

    const int bh   = blockIdx.x;
    const int tid  = threadIdx.x;
    const int warp = tid >> 5;
    const int lane = tid & 31;
    const int causal = *causal_p;
    const float scale = 0.03608439182435161f;  // 1/sqrt(768)

    const float* Qg = Qg_ + (size_t)bh * (S_ * D_);
    const float* Kg = Kg_ + (size_t)bh * (S_ * D_);
    const float* Vg = Vg_ + (size_t)bh * (S_ * D_);
    float*     outg = outg_ + (size_t)bh * (S_ * D_);

    // ---------------- Stage A: load Q, K, E (float4, coalesced) ----------------------
    #pragma unroll 1
    for (int t = tid; t < (S_ * D_) / 4; t += NT_) {
        int e = t << 2, r = e >> 6, c = e & 63;
        *(float4*)&sQ[r * QSTR_ + c] = *(const float4*)&Qg[e];
        *(float4*)&sK[r * QSTR_ + c] = *(const float4*)&Kg[e];
    }
    #pragma unroll 1
    for (int t = tid; t < (ER_ * D_) / 4; t += NT_) {
        int e = t << 2, r = e >> 6, c = e & 63;
        *(float4*)&sEV[r * QSTR_ + c] = *(const float4*)&Eg[e];
    }
    __syncthreads();

    // ---------------- Stage C: fused (QK^T + rel-bias) + mask -> sP ------------------
    // logits[i][j] = Q[i].K[j] + Q[i].E[S-1+i-j]   (rel index always in [0, 2S-2])
    for (int tile = warp; tile < NTILE_; tile += NW_) {
        const int i0   = tile * 4;
        const int imax = min(i0 + 3, S_ - 1);
        const int njj  = causal ? ((imax >> 5) + 1) : 3;   // skip fully-masked j-groups

        float acc[4][3];
        #pragma unroll
        for (int r = 0; r < 4; r++) { acc[r][0] = acc[r][1] = acc[r][2] = 0.f; }

        int ival[4], ri[4];
        #pragma unroll
        for (int r = 0; r < 4; r++) { ival[r] = min(i0 + r, S_ - 1); ri[r] = ival[r] * QSTR_; }
        int jval[3], ki[3];
        #pragma unroll
        for (int jj = 0; jj < 3; jj++) { jval[jj] = min(lane + 32 * jj, S_ - 1); ki[jj] = jval[jj] * QSTR_; }
        int ei[4][3];
        #pragma unroll
        for (int r = 0; r < 4; r++)
            #pragma unroll
            for (int jj = 0; jj < 3; jj++)
                ei[r][jj] = (S_ - 1 + ival[r] - jval[jj]) * QSTR_;   // in [0, 2S-2]

        for (int d = 0; d < D_; d += 4) {
            float4 q[4];
            #pragma unroll
            for (int r = 0; r < 4; r++) q[r] = *(const float4*)&sQ[ri[r] + d];
            #pragma unroll
            for (int jj = 0; jj < 3; jj++) {
                if (jj < njj) {
                    float4 k4 = *(const float4*)&sK[ki[jj] + d];
                    #pragma unroll
                    for (int r = 0; r < 4; r++) {
                        float4 e4 = *(const float4*)&sEV[ei[r][jj] + d];
                        float a = acc[r][jj];
                        a = fmaf(q[r].x, k4.x, a); a = fmaf(q[r].x, e4.x, a);
                        a = fmaf(q[r].y, k4.y, a); a = fmaf(q[r].y, e4.y, a);
                        a = fmaf(q[r].z, k4.z, a); a = fmaf(q[r].z, e4.z, a);
                        a = fmaf(q[r].w, k4.w, a); a = fmaf(q[r].w, e4.w, a);
                        acc[r][jj] = a;
                    }
                }
            }
        }
        #pragma unroll
        for (int r = 0; r < 4; r++) {
            int i = i0 + r;
            if (i < S_) {
                #pragma unroll
                for (int jj = 0; jj < 3; jj++) {
                    int j = lane + 32 * jj;
                    if (j < S_) {
                        float v = (causal && j > i) ? -1.0e9f : acc[r][jj] * scale;
                        sP[i * PSTR_ + j] = v;
                    }
                }
            }
        }
    }
    __syncthreads();   // E reads done -> safe to overwrite with V; sP complete for softmax

    // ---------------- V load (overwrites E region rows 0..80) ------------------------
    #pragma unroll 1
    for (int t = tid; t < (S_ * D_) / 4; t += NT_) {
        int e = t << 2, r = e >> 6, c = e & 63;
        *(float4*)&sEV[r * QSTR_ + c] = *(const float4*)&Vg[e];
    }

    // ---------------- Softmax (one warp per row) -------------------------------------
    for (int i = warp; i < S_; i += NW_) {
        float* row = &sP[i * PSTR_];
        float a = row[lane];
        float b = row[lane + 32];
        float c = (lane < S_ - 64) ? row[lane + 64] : -3.0e38f;
        float m = fmaxf(a, fmaxf(b, c));
        #pragma unroll
        for (int o = 16; o > 0; o >>= 1) m = fmaxf(m, __shfl_xor_sync(0xffffffffu, m, o));
        float e0 = expf(a - m), e1 = expf(b - m);
        float e2 = (lane < S_ - 64) ? expf(c - m) : 0.f;
        float s = e0 + e1 + e2;
        #pragma unroll
        for (int o = 16; o > 0; o >>= 1) s += __shfl_xor_sync(0xffffffffu, s, o);
        float inv = 1.0f / s;
        row[lane]      = e0 * inv;
        row[lane + 32] = e1 * inv;
        if (lane < S_ - 64) row[lane + 64] = e2 * inv;
    }
    __syncthreads();

    // ---------------- Stage E: PV  out[i][d] = sum_j P[i][j] * V[j][d] ---------------
    for (int tile = warp; tile < NTILE_; tile += NW_) {
        const int i0   = tile * 4;
        const int imax = min(i0 + 3, S_ - 1);
        const int jmax = causal ? imax : (S_ - 1);   // masked P entries are exactly 0
        float2 acc[4];
        #pragma unroll
        for (int r = 0; r < 4; r++) { acc[r].x = 0.f; acc[r].y = 0.f; }
        int ri[4];
        #pragma unroll
        for (int r = 0; r < 4; r++) ri[r] = min(i0 + r, S_ - 1) * PSTR_;
        const int dcol = 2 * lane;

        #pragma unroll 2
        for (int j = 0; j <= jmax; j++) {
            float2 v = *(const float2*)&sEV[j * QSTR_ + dcol];
            #pragma unroll
            for (int r = 0; r < 4; r++) {
                float p = sP[ri[r] + j];
                acc[r].x = fmaf(p, v.x, acc[r].x);
                acc[r].y = fmaf(p, v.y, acc[r].y);
            }
        }
        #pragma unroll
        for (int r = 0; r < 4; r++) {
            int i = i0 + r;
            if (i < S_) *(float2*)&outg[i * D_ + dcol] = acc[r];
        }
    }
}

extern "C" void kernel_launch(void* const* d_in, const int* in_sizes, int n_in,
                              void* d_out, int out_size)
{
    const float* Q  = (const float*)d_in[0];
    const float* K  = (const float*)d_in[1];
    const float* V  = (const float*)d_in[2];
    const float* E  = (const float*)d_in[3];
    const int*   uc = (const int*)d_in[4];
    float* out = (float*)d_out;

    const int nbh = out_size / (S_ * D_);   // 4096 for the bench shape
    const size_t smem = (size_t)SMEM_FLOATS * sizeof(float);  // 114644 B -> 2 CTAs/SM

    cudaFuncSetAttribute(rpsa_kernel, cudaFuncAttributeMaxDynamicSharedMemorySize, (int)smem);
    rpsa_kernel<<<nbh, NT_, smem>>>(Q, K, V, E, uc, out);
}